// round 14
// baseline (speedup 1.0000x reference)
#include <cuda_runtime.h>
#include <cuda_bf16.h>
#include <math.h>

#define BB 64
#define JJ 32
#define NV 4096
#define QD 130
#define KD 128
#define VD 130
#define HH 4
#define QROWS 128              // J*H rows of q per batch
#define OST 136                // osum row stride (130 vals + denom @130 + pad)
#define NSPLIT 16              // n-splits (accumulated via red.global.add)
#define CHUNK 64
#define NCHUNKS ((NV / NSPLIT) / CHUNK)   // 4
// fold log2(e)/sqrt(128) into q so p = exp2f(score)
#define QSCALE (1.4426950408889634f / 11.313708498984761f)

// ---------------- device scratch (static: no runtime allocation) ----------
__device__ __nv_bfloat16 g_Qh[BB * QROWS * KD];    // [b][q][d] hi
__device__ __nv_bfloat16 g_Ql[BB * QROWS * KD];    // [b][q][d] lo
__device__ float g_osum[(size_t)BB * QROWS * OST]; // accumulated O (4.25 MB)
__device__ int   g_flags[3];                       // mask-dtype evidence flags

// split-pack via bf16x2 CVT: two floats -> (hi pair, lo pair) packed u32
__device__ __forceinline__ void splitpack2(float x, float y, unsigned& hi, unsigned& lo) {
    unsigned h;
    asm("cvt.rn.bf16x2.f32 %0, %1, %2;" : "=r"(h) : "f"(y), "f"(x));  // x->low, y->high
    float hx = __uint_as_float(h << 16);
    float hy = __uint_as_float(h & 0xFFFF0000u);
    float rx = x - hx;
    float ry = y - hy;
    unsigned l;
    asm("cvt.rn.bf16x2.f32 %0, %1, %2;" : "=r"(l) : "f"(ry), "f"(rx));
    hi = h; lo = l;
}

#define MMA4(C, A0, A1, A2, A3, B0, B1) \
    asm volatile("mma.sync.aligned.m16n8k16.row.col.f32.bf16.bf16.f32 " \
        "{%0,%1,%2,%3}, {%4,%5,%6,%7}, {%8,%9}, {%0,%1,%2,%3};" \
        : "+f"((C)[0]), "+f"((C)[1]), "+f"((C)[2]), "+f"((C)[3]) \
        : "r"(A0), "r"(A1), "r"(A2), "r"(A3), "r"(B0), "r"(B1))

#define LDSM_X4(R0, R1, R2, R3, ADDR) \
    asm volatile("ldmatrix.sync.aligned.m8n8.x4.shared.b16 {%0,%1,%2,%3}, [%4];" \
        : "=r"(R0), "=r"(R1), "=r"(R2), "=r"(R3) : "r"(ADDR))

#define LDSM_X2(R0, R1, ADDR) \
    asm volatile("ldmatrix.sync.aligned.m8n8.x2.shared.b16 {%0,%1}, [%2];" \
        : "=r"(R0), "=r"(R1) : "r"(ADDR))

__device__ __forceinline__ void cpa16(unsigned dst, const void* src) {
    asm volatile("cp.async.cg.shared.global [%0], [%1], 16;" :: "r"(dst), "l"(src));
}

__device__ __forceinline__ void redadd(float* p, float v) {
    asm volatile("red.global.add.f32 [%0], %1;" :: "l"(p), "f"(v) : "memory");
}

// ---------------- mask dtype detection (deterministic, data-driven) -------
__global__ void classify_mask(const uint4* __restrict__ m) {
    int gid = blockIdx.x * 256 + threadIdx.x;   // 0..16383
    uint4 v = m[gid];
    unsigned wrd[4] = {v.x, v.y, v.z, v.w};
    bool l0 = false, l1 = false, l2 = false;
#pragma unroll
    for (int wI = 0; wI < 4; wI++) {
        unsigned x = wrd[wI];
        unsigned b0 = x & 0xFF, b1 = (x >> 8) & 0xFF, b2 = (x >> 16) & 0xFF, b3 = x >> 24;
        if (b1 == 0x3F) l0 = true;
        if (b0 == 0x3F || b1 == 0x3F || b2 == 0x3F || b3 == 0x3F) l1 = true;
        if (b1 | b2 | b3) l2 = true;
    }
    unsigned m0 = __ballot_sync(0xFFFFFFFFu, l0);
    unsigned m1 = __ballot_sync(0xFFFFFFFFu, l1);
    unsigned m2 = __ballot_sync(0xFFFFFFFFu, l2);
    if ((threadIdx.x & 31) == 0) {
        if (m0) atomicOr(&g_flags[0], 1);
        if (m1) atomicOr(&g_flags[1], 1);
        if (m2) atomicOr(&g_flags[2], 1);
    }
}

// zero the O accumulator (must precede fused_attn each replay)
__global__ void __launch_bounds__(256) zero_osum() {
    size_t i4 = (size_t)blockIdx.x * 256 + threadIdx.x;
    ((float4*)g_osum)[i4] = make_float4(0.f, 0.f, 0.f, 0.f);
}

// ---------------- kernel A: q encoder MLP, 8 joints per block --------------
__global__ void __launch_bounds__(128) encoder_kernel(
    const float* __restrict__ jq,
    const float* __restrict__ W1, const float* __restrict__ b1,
    const float* __restrict__ W2, const float* __restrict__ b2) {
    __shared__ float xs[8][132];
    __shared__ float hs[8][68];
    int bid = blockIdx.x;            // b*4 + jg
    int b = bid >> 2, jg = (bid & 3) * 8;
    int tid = threadIdx.x;

    for (int idx = tid; idx < 8 * QD; idx += 128) {
        int jj = idx / QD, d = idx - jj * QD;
        xs[jj][d] = jq[((size_t)(b * JJ + jg + jj)) * QD + d];
    }
    __syncthreads();
    {
        int o = tid & 63, jb = tid >> 6;
        float s0 = b1[o], s1 = s0, s2 = s0, s3 = s0;
        for (int r = 0; r < QD; r++) {
            float wv = W1[r * 64 + o];
            s0 += xs[jb][r] * wv;
            s1 += xs[jb + 2][r] * wv;
            s2 += xs[jb + 4][r] * wv;
            s3 += xs[jb + 6][r] * wv;
        }
        hs[jb][o]     = fmaxf(s0, 0.0f);
        hs[jb + 2][o] = fmaxf(s1, 0.0f);
        hs[jb + 4][o] = fmaxf(s2, 0.0f);
        hs[jb + 6][o] = fmaxf(s3, 0.0f);
    }
    __syncthreads();
    int k0 = tid * 4;
    float s[8][4];
    float bb0 = b2[k0], bb1 = b2[k0 + 1], bb2 = b2[k0 + 2], bb3 = b2[k0 + 3];
#pragma unroll
    for (int jj = 0; jj < 8; jj++) {
        s[jj][0] = bb0; s[jj][1] = bb1; s[jj][2] = bb2; s[jj][3] = bb3;
    }
    for (int r = 0; r < 64; r++) {
        float4 w = *(const float4*)(W2 + r * 512 + k0);
#pragma unroll
        for (int jj = 0; jj < 8; jj++) {
            float hv = hs[jj][r];
            s[jj][0] += hv * w.x; s[jj][1] += hv * w.y;
            s[jj][2] += hv * w.z; s[jj][3] += hv * w.w;
        }
    }
#pragma unroll
    for (int jj = 0; jj < 8; jj++) {
#pragma unroll
        for (int u = 0; u < 4; u++) {
            int k = k0 + u;
            int head = k >> 7, d = k & 127;
            int qi = (jg + jj) * 4 + head;
            float q = s[jj][u] * QSCALE;
            __nv_bfloat16 h = __float2bfloat16(q);
            g_Qh[((size_t)b * QROWS + qi) * KD + d] = h;
            g_Ql[((size_t)b * QROWS + qi) * KD + d] =
                __float2bfloat16(q - __bfloat162float(h));
        }
    }
}

// ---------------- fused attention kernel (R9 loop order) --------------------
#define OFF_QH   0
#define OFF_QL   34816
#define OFF_KH   69632
#define OFF_KL   87040
#define OFF_VH   104448
#define OFF_VL   124032
#define OFF_KSTA 143616     // f32[8192]  raw K chunk
#define OFF_VSTA 176384     // f32[8320]  raw V chunk
#define OFF_KEEP 209664     // f32[256]   keep for all 4 chunks
#define SM_TOTAL 210688
__global__ void __launch_bounds__(256) fused_attn_kernel(
    const float* __restrict__ Kg, const float* __restrict__ Vg,
    const void* __restrict__ mk) {
    extern __shared__ unsigned char smraw[];
    unsigned* Qh32 = (unsigned*)(smraw + OFF_QH);   // 128 x 68 u32
    unsigned* Ql32 = (unsigned*)(smraw + OFF_QL);
    unsigned* Kh32 = (unsigned*)(smraw + OFF_KH);   // 64 x 68 u32
    unsigned* Kl32 = (unsigned*)(smraw + OFF_KL);
    unsigned* Vh32 = (unsigned*)(smraw + OFF_VH);   // 136 x 36 u32 [v][n]
    unsigned* Vl32 = (unsigned*)(smraw + OFF_VL);
    float* Ksta    = (float*)(smraw + OFF_KSTA);
    float* Vsta    = (float*)(smraw + OFF_VSTA);
    float* keepAll = (float*)(smraw + OFF_KEEP);

    int split = blockIdx.x, b = blockIdx.y;
    int tid = threadIdx.x;
    int w = tid >> 5, l = tid & 31, g = l >> 2, t = l & 3;
    int m0 = w * 16;
    int nblk = split * (NV / NSPLIT);

    int rowA = l & 15;
    int colA = (l >> 4) * 4;
    int rowB = (l & 7) + ((l >> 4) << 3);
    int colB = ((l >> 3) & 1) * 4;

    unsigned QhU = (unsigned)__cvta_generic_to_shared(Qh32);
    unsigned QlU = (unsigned)__cvta_generic_to_shared(Ql32);
    unsigned KhU = (unsigned)__cvta_generic_to_shared(Kh32);
    unsigned KlU = (unsigned)__cvta_generic_to_shared(Kl32);
    unsigned VhU = (unsigned)__cvta_generic_to_shared(Vh32);
    unsigned VlU = (unsigned)__cvta_generic_to_shared(Vl32);
    unsigned KstaU = (unsigned)__cvta_generic_to_shared(Ksta);
    unsigned VstaU = (unsigned)__cvta_generic_to_shared(Vsta);

    unsigned aH  = QhU + (((m0 + rowA) * 68) + colA) * 4;
    unsigned aL  = QlU + (((m0 + rowA) * 68) + colA) * 4;
    unsigned bKh = KhU + ((rowB * 68) + colB) * 4;
    unsigned bKl = KlU + ((rowB * 68) + colB) * 4;
    unsigned bVh = VhU + ((rowB * 36) + colB) * 4;
    unsigned bVl = VlU + ((rowB * 36) + colB) * 4;
    unsigned bV2h = VhU + (((128 + (l & 7)) * 36) + colB) * 4;
    unsigned bV2l = VlU + (((128 + (l & 7)) * 36) + colB) * 4;

    // ---- prologue: cp.async Q + chunk0 K/V; keep computed inline ----
    {
        const char* srcH = (const char*)((const unsigned*)g_Qh + (size_t)b * (QROWS * KD / 2));
        const char* srcL = (const char*)((const unsigned*)g_Ql + (size_t)b * (QROWS * KD / 2));
#pragma unroll
        for (int i = 0; i < 8; i++) {
            int idx = tid + i * 256;
            int r = idx >> 4, c16 = idx & 15;
            unsigned dofs = (unsigned)(r * 272 + c16 * 16);
            cpa16(QhU + dofs, srcH + idx * 16);
            cpa16(QlU + dofs, srcL + idx * 16);
        }
        const char* ksrc = (const char*)(Kg + ((size_t)b * NV + nblk) * KD);
        const char* vsrc = (const char*)(Vg + ((size_t)b * NV + nblk) * VD);
#pragma unroll
        for (int i = 0; i < 8; i++) {
            int off = (tid + i * 256) * 16;
            cpa16(KstaU + off, ksrc + off);
        }
#pragma unroll
        for (int i = 0; i < 9; i++) {
            int idx = tid + i * 256;
            if (idx < 2080) cpa16(VstaU + idx * 16, vsrc + idx * 16);
        }
        asm volatile("cp.async.commit_group;" ::: "memory");

        int gi = b * NV + nblk + tid;
        bool masked;
        if (g_flags[0])      masked = ((const unsigned short*)mk)[gi] != 0;
        else if (g_flags[1]) masked = ((const float*)mk)[gi]          != 0.0f;
        else if (g_flags[2]) masked = ((const unsigned char*)mk)[gi]  != 0;
        else                 masked = ((const int*)mk)[gi]            != 0;
        keepAll[tid] = masked ? 0.0f : 1.0f;
    }
    for (int i = tid; i < 192; i += 256) {
        int v = 130 + (i >> 5), np = i & 31;
        Vh32[v * 36 + np] = (v == 130) ? 0x3F803F80u : 0u;
        Vl32[v * 36 + np] = 0u;
    }

    float accO[17][4];
#pragma unroll
    for (int i = 0; i < 17; i++) { accO[i][0] = accO[i][1] = accO[i][2] = accO[i][3] = 0.0f; }

    for (int c = 0; c < NCHUNKS; c++) {
        asm volatile("cp.async.wait_group 0;" ::: "memory");
        __syncthreads();

        // ---- K convert ----
#pragma unroll
        for (int i = 0; i < 8; i++) {
            int idx = tid + i * 256;
            int n = idx >> 5;
            int d4 = (idx & 31) * 4;
            float4 v = *(const float4*)(Ksta + n * 128 + d4);
            unsigned h0, l0v, h1, l1v;
            splitpack2(v.x, v.y, h0, l0v);
            splitpack2(v.z, v.w, h1, l1v);
            int o = n * 68 + (d4 >> 1);
            Kh32[o] = h0; Kh32[o + 1] = h1;
            Kl32[o] = l0v; Kl32[o + 1] = l1v;
        }
        // ---- V convert ----
#pragma unroll
        for (int i = 0; i < 17; i++) {
            int p = tid + i * 256;
            if (p < 4160) {
                int np = p / 130;
                int v = p - np * 130;
                float x = Vsta[(2 * np) * 130 + v];
                float y = Vsta[(2 * np + 1) * 130 + v];
                unsigned h, lo;
                splitpack2(x, y, h, lo);
                Vh32[v * 36 + np] = h;
                Vl32[v * 36 + np] = lo;
            }
        }
        __syncthreads();

        // ---- prefetch next chunk (overlaps MMAs below) ----
        if (c < NCHUNKS - 1) {
            int n1 = nblk + (c + 1) * CHUNK;
            const char* ksrc = (const char*)(Kg + ((size_t)b * NV + n1) * KD);
            const char* vsrc = (const char*)(Vg + ((size_t)b * NV + n1) * VD);
#pragma unroll
            for (int i = 0; i < 8; i++) {
                int off = (tid + i * 256) * 16;
                cpa16(KstaU + off, ksrc + off);
            }
#pragma unroll
            for (int i = 0; i < 9; i++) {
                int idx = tid + i * 256;
                if (idx < 2080) cpa16(VstaU + idx * 16, vsrc + idx * 16);
            }
            asm volatile("cp.async.commit_group;" ::: "memory");
        }

        const float* keepc = keepAll + c * 64;

        // ---- QK ----
        float accS[8][4];
#pragma unroll
        for (int i = 0; i < 8; i++) { accS[i][0] = accS[i][1] = accS[i][2] = accS[i][3] = 0.0f; }

#pragma unroll
        for (int ks = 0; ks < 8; ks++) {
            unsigned ah0, ah1, ah2, ah3, al0, al1, al2, al3;
            LDSM_X4(ah0, ah1, ah2, ah3, aH + ks * 32);
            LDSM_X4(al0, al1, al2, al3, aL + ks * 32);
#pragma unroll
            for (int ntp = 0; ntp < 4; ntp++) {
                unsigned h0, h1, h2, h3, q0, q1, q2, q3;
                LDSM_X4(h0, h1, h2, h3, bKh + ntp * 4352 + ks * 32);
                LDSM_X4(q0, q1, q2, q3, bKl + ntp * 4352 + ks * 32);
                MMA4(accS[2 * ntp], ah0, ah1, ah2, ah3, h0, h1);
                MMA4(accS[2 * ntp], al0, al1, al2, al3, h0, h1);
                MMA4(accS[2 * ntp], ah0, ah1, ah2, ah3, q0, q1);
                MMA4(accS[2 * ntp + 1], ah0, ah1, ah2, ah3, h2, h3);
                MMA4(accS[2 * ntp + 1], al0, al1, al2, al3, h2, h3);
                MMA4(accS[2 * ntp + 1], ah0, ah1, ah2, ah3, q2, q3);
            }
        }

        // ---- epilogue: P = exp2(S)*keep, re-split ----
        unsigned phA[8], phB[8], plA[8], plB[8];
#pragma unroll
        for (int nt = 0; nt < 8; nt++) {
            int c0 = nt * 8 + 2 * t;
            float k0f = keepc[c0], k1f = keepc[c0 + 1];
            float p0 = exp2f(accS[nt][0]) * k0f;
            float p1 = exp2f(accS[nt][1]) * k1f;
            float p2 = exp2f(accS[nt][2]) * k0f;
            float p3 = exp2f(accS[nt][3]) * k1f;
            splitpack2(p0, p1, phA[nt], plA[nt]);
            splitpack2(p2, p3, phB[nt], plB[nt]);
        }

        // ---- PV ----
#pragma unroll
        for (int ks = 0; ks < 4; ks++) {
            unsigned ah0 = phA[2 * ks], ah1 = phB[2 * ks];
            unsigned ah2 = phA[2 * ks + 1], ah3 = phB[2 * ks + 1];
            unsigned al0 = plA[2 * ks], al1 = plB[2 * ks];
            unsigned al2 = plA[2 * ks + 1], al3 = plB[2 * ks + 1];
#pragma unroll
            for (int vtp = 0; vtp < 8; vtp++) {
                unsigned h0, h1, h2, h3, q0, q1, q2, q3;
                LDSM_X4(h0, h1, h2, h3, bVh + vtp * 2304 + ks * 32);
                LDSM_X4(q0, q1, q2, q3, bVl + vtp * 2304 + ks * 32);
                MMA4(accO[2 * vtp], ah0, ah1, ah2, ah3, h0, h1);
                MMA4(accO[2 * vtp], al0, al1, al2, al3, h0, h1);
                MMA4(accO[2 * vtp], ah0, ah1, ah2, ah3, q0, q1);
                MMA4(accO[2 * vtp + 1], ah0, ah1, ah2, ah3, h2, h3);
                MMA4(accO[2 * vtp + 1], al0, al1, al2, al3, h2, h3);
                MMA4(accO[2 * vtp + 1], ah0, ah1, ah2, ah3, q2, q3);
            }
            {
                unsigned h0, h1, q0, q1;
                LDSM_X2(h0, h1, bV2h + ks * 32);
                LDSM_X2(q0, q1, bV2l + ks * 32);
                MMA4(accO[16], ah0, ah1, ah2, ah3, h0, h1);
                MMA4(accO[16], al0, al1, al2, al3, h0, h1);
                MMA4(accO[16], ah0, ah1, ah2, ah3, q0, q1);
            }
        }
    }

    // accumulate O tile directly into g_osum (no per-split buffers)
    float* orow0 = g_osum + ((size_t)b * QROWS + m0 + g) * OST;
    float* orow1 = orow0 + 8 * OST;
#pragma unroll
    for (int vt = 0; vt < 17; vt++) {
        int v0 = vt * 8 + 2 * t;
        redadd(orow0 + v0,     accO[vt][0]);
        redadd(orow0 + v0 + 1, accO[vt][1]);
        redadd(orow1 + v0,     accO[vt][2]);
        redadd(orow1 + v0 + 1, accO[vt][3]);
    }
}

// ---------------- kernel C: per-batch-half normalize + MLP -----------------
// grid 128 (b*2+half), 256 threads; reads compact g_osum + W3 once.
__global__ void __launch_bounds__(256) mlp_kernel(
    const float* __restrict__ W3, const float* __restrict__ b3,
    const float* __restrict__ W4, const float* __restrict__ b4,
    const float* __restrict__ W5, const float* __restrict__ b5,
    float* __restrict__ out) {
    __shared__ float os2[64 * 136];    // 16 joints x 4 heads x 136
    __shared__ float rcp[64];
    __shared__ float h1[16 * 64];
    __shared__ float h2[16 * 32];
    int bid = blockIdx.x;            // b*2 + half
    int b = bid >> 1, half = bid & 1;
    int tid = threadIdx.x;
    size_t base4 = (((size_t)b * QROWS + half * 64) * OST) / 4;

    for (int i4 = tid; i4 < 2176; i4 += 256)
        *(float4*)&os2[i4 * 4] = ((const float4*)g_osum)[base4 + i4];
    __syncthreads();
    if (tid < 64) rcp[tid] = __frcp_rn(os2[tid * 136 + 130]);
    __syncthreads();
    for (int idx = tid; idx < 64 * 130; idx += 256) {
        int r = idx / 130, v = idx - r * 130;
        os2[r * 136 + v] *= rcp[r];
    }
    __syncthreads();

    // layer 1: [16 j][520] @ W3[520][64]
    {
        int o = tid & 63, jq4 = tid >> 6;
        float s0 = b3[o], s1 = s0, s2 = s0, s3 = s0;
        for (int h = 0; h < 4; h++) {
            const float* osr = os2 + (jq4 * 16 + h) * 136;
            const float* w3r = W3 + h * 130 * 64 + o;
            for (int v = 0; v < 130; v++) {
                float wv = w3r[v * 64];
                s0 += osr[v] * wv;
                s1 += osr[v + 544] * wv;
                s2 += osr[v + 1088] * wv;
                s3 += osr[v + 1632] * wv;
            }
        }
        int j0 = jq4 * 4;
        h1[(j0 + 0) * 64 + o] = fmaxf(s0, 0.0f);
        h1[(j0 + 1) * 64 + o] = fmaxf(s1, 0.0f);
        h1[(j0 + 2) * 64 + o] = fmaxf(s2, 0.0f);
        h1[(j0 + 3) * 64 + o] = fmaxf(s3, 0.0f);
    }
    __syncthreads();

#pragma unroll
    for (int rep = 0; rep < 2; rep++) {
        int it = tid + rep * 256;
        int j = it >> 5, o = it & 31;
        float s = b4[o];
#pragma unroll
        for (int r = 0; r < 64; r++) s += h1[j * 64 + r] * W4[r * 32 + o];
        h2[j * 32 + o] = fmaxf(s, 0.0f);
    }
    __syncthreads();

    int wid = tid >> 5, lane = tid & 31;
#pragma unroll
    for (int rep = 0; rep < 2; rep++) {
        int j = wid + rep * 8;
        float v = h2[j * 32 + lane] * W5[lane];
#pragma unroll
        for (int off = 16; off; off >>= 1) v += __shfl_down_sync(0xffffffffu, v, off);
        if (lane == 0) out[b * JJ + half * 16 + j] = v + b5[0];
    }
    // reset mask-dtype flags for next graph replay
    if (bid == 0 && tid < 3) g_flags[tid] = 0;
}

// ---------------- launch ----------------------------------------------------
extern "C" void kernel_launch(void* const* d_in, const int* in_sizes, int n_in,
                              void* d_out, int out_size) {
    const float* jq = (const float*)d_in[0];
    const float* Kg = (const float*)d_in[1];
    const float* Vg = (const float*)d_in[2];
    const void*  mk = d_in[3];
    const float* W1 = (const float*)d_in[4];
    const float* b1 = (const float*)d_in[5];
    const float* W2 = (const float*)d_in[6];
    const float* b2 = (const float*)d_in[7];
    const float* W3 = (const float*)d_in[8];
    const float* b3 = (const float*)d_in[9];
    const float* W4 = (const float*)d_in[10];
    const float* b4 = (const float*)d_in[11];
    const float* W5 = (const float*)d_in[12];
    const float* b5 = (const float*)d_in[13];
    float* out = (float*)d_out;

    classify_mask<<<64, 256>>>((const uint4*)mk);
    zero_osum<<<(BB * QROWS * OST / 4) / 256, 256>>>();
    encoder_kernel<<<BB * 4, 128>>>(jq, W1, b1, W2, b2);

    cudaFuncSetAttribute(fused_attn_kernel,
                         cudaFuncAttributeMaxDynamicSharedMemorySize, SM_TOTAL);
    dim3 g1(NSPLIT, BB);
    fused_attn_kernel<<<g1, 256, SM_TOTAL>>>(Kg, Vg, mk);

    mlp_kernel<<<BB * 2, 256>>>(W3, b3, W4, b4, W5, b5, out);
}

// round 15
// speedup vs baseline: 1.2094x; 1.2094x over previous
#include <cuda_runtime.h>
#include <cuda_bf16.h>
#include <cuda_fp16.h>
#include <math.h>

#define BB 64
#define JJ 32
#define NV 4096
#define QD 130
#define KD 128
#define VD 130
#define HH 4
#define QROWS 128              // J*H rows of q per batch
#define OST 136                // osum row stride (130 vals + denom @130 + pad)
#define NSPLIT 16              // n-splits (accumulated via red.global.add)
#define CHUNK 64
#define NCHUNKS ((NV / NSPLIT) / CHUNK)   // 4
// fold log2(e)/sqrt(128) into q so p = exp2f(score)
#define QSCALE (1.4426950408889634f / 11.313708498984761f)
#define PBIAS 3.0f             // p = exp2(S - PBIAS); cancels in normalization

// ---------------- device scratch (static: no runtime allocation) ----------
__device__ __half g_Qh[BB * QROWS * KD];           // [b][q][d] hi (fp16)
__device__ __half g_Ql[BB * QROWS * KD];           // [b][q][d] lo (fp16)
__device__ float g_osum[(size_t)BB * QROWS * OST]; // accumulated O (4.25 MB)
__device__ int   g_flags[3];                       // mask-dtype evidence flags

// pack two floats -> fp16x2 u32 (x -> low half, y -> high half)
__device__ __forceinline__ unsigned pack2H(float x, float y) {
    unsigned r;
    asm("cvt.rn.f16x2.f32 %0, %1, %2;" : "=r"(r) : "f"(y), "f"(x));
    return r;
}
// fp16 split-pack: hi = fp16(x,y), lo = fp16 residuals
__device__ __forceinline__ void splitpackH(float x, float y, unsigned& hi, unsigned& lo) {
    unsigned h = pack2H(x, y);
    __half2 hh = *reinterpret_cast<__half2*>(&h);
    float2 hf = __half22float2(hh);
    lo = pack2H(x - hf.x, y - hf.y);
    hi = h;
}

#define MMA4(C, A0, A1, A2, A3, B0, B1) \
    asm volatile("mma.sync.aligned.m16n8k16.row.col.f32.f16.f16.f32 " \
        "{%0,%1,%2,%3}, {%4,%5,%6,%7}, {%8,%9}, {%0,%1,%2,%3};" \
        : "+f"((C)[0]), "+f"((C)[1]), "+f"((C)[2]), "+f"((C)[3]) \
        : "r"(A0), "r"(A1), "r"(A2), "r"(A3), "r"(B0), "r"(B1))

#define LDSM_X4(R0, R1, R2, R3, ADDR) \
    asm volatile("ldmatrix.sync.aligned.m8n8.x4.shared.b16 {%0,%1,%2,%3}, [%4];" \
        : "=r"(R0), "=r"(R1), "=r"(R2), "=r"(R3) : "r"(ADDR))

#define LDSM_X2(R0, R1, ADDR) \
    asm volatile("ldmatrix.sync.aligned.m8n8.x2.shared.b16 {%0,%1}, [%2];" \
        : "=r"(R0), "=r"(R1) : "r"(ADDR))

__device__ __forceinline__ void cpa16(unsigned dst, const void* src) {
    asm volatile("cp.async.cg.shared.global [%0], [%1], 16;" :: "r"(dst), "l"(src));
}

__device__ __forceinline__ void redadd(float* p, float v) {
    asm volatile("red.global.add.f32 [%0], %1;" :: "l"(p), "f"(v) : "memory");
}

// ---------------- mask dtype detection (deterministic, data-driven) -------
__global__ void classify_mask(const uint4* __restrict__ m) {
    int gid = blockIdx.x * 256 + threadIdx.x;   // 0..16383
    uint4 v = m[gid];
    unsigned wrd[4] = {v.x, v.y, v.z, v.w};
    bool l0 = false, l1 = false, l2 = false;
#pragma unroll
    for (int wI = 0; wI < 4; wI++) {
        unsigned x = wrd[wI];
        unsigned b0 = x & 0xFF, b1 = (x >> 8) & 0xFF, b2 = (x >> 16) & 0xFF, b3 = x >> 24;
        if (b1 == 0x3F) l0 = true;
        if (b0 == 0x3F || b1 == 0x3F || b2 == 0x3F || b3 == 0x3F) l1 = true;
        if (b1 | b2 | b3) l2 = true;
    }
    unsigned m0 = __ballot_sync(0xFFFFFFFFu, l0);
    unsigned m1 = __ballot_sync(0xFFFFFFFFu, l1);
    unsigned m2 = __ballot_sync(0xFFFFFFFFu, l2);
    if ((threadIdx.x & 31) == 0) {
        if (m0) atomicOr(&g_flags[0], 1);
        if (m1) atomicOr(&g_flags[1], 1);
        if (m2) atomicOr(&g_flags[2], 1);
    }
}

// zero the O accumulator (must precede fused_attn each replay)
__global__ void __launch_bounds__(256) zero_osum() {
    size_t i4 = (size_t)blockIdx.x * 256 + threadIdx.x;
    ((float4*)g_osum)[i4] = make_float4(0.f, 0.f, 0.f, 0.f);
}

// ---------------- kernel A: q encoder MLP, 8 joints per block --------------
__global__ void __launch_bounds__(128) encoder_kernel(
    const float* __restrict__ jq,
    const float* __restrict__ W1, const float* __restrict__ b1,
    const float* __restrict__ W2, const float* __restrict__ b2) {
    __shared__ float xs[8][132];
    __shared__ float hs[8][68];
    int bid = blockIdx.x;            // b*4 + jg
    int b = bid >> 2, jg = (bid & 3) * 8;
    int tid = threadIdx.x;

    for (int idx = tid; idx < 8 * QD; idx += 128) {
        int jj = idx / QD, d = idx - jj * QD;
        xs[jj][d] = jq[((size_t)(b * JJ + jg + jj)) * QD + d];
    }
    __syncthreads();
    {
        int o = tid & 63, jb = tid >> 6;
        float s0 = b1[o], s1 = s0, s2 = s0, s3 = s0;
        for (int r = 0; r < QD; r++) {
            float wv = W1[r * 64 + o];
            s0 += xs[jb][r] * wv;
            s1 += xs[jb + 2][r] * wv;
            s2 += xs[jb + 4][r] * wv;
            s3 += xs[jb + 6][r] * wv;
        }
        hs[jb][o]     = fmaxf(s0, 0.0f);
        hs[jb + 2][o] = fmaxf(s1, 0.0f);
        hs[jb + 4][o] = fmaxf(s2, 0.0f);
        hs[jb + 6][o] = fmaxf(s3, 0.0f);
    }
    __syncthreads();
    int k0 = tid * 4;
    float s[8][4];
    float bb0 = b2[k0], bb1 = b2[k0 + 1], bb2 = b2[k0 + 2], bb3 = b2[k0 + 3];
#pragma unroll
    for (int jj = 0; jj < 8; jj++) {
        s[jj][0] = bb0; s[jj][1] = bb1; s[jj][2] = bb2; s[jj][3] = bb3;
    }
    for (int r = 0; r < 64; r++) {
        float4 w = *(const float4*)(W2 + r * 512 + k0);
#pragma unroll
        for (int jj = 0; jj < 8; jj++) {
            float hv = hs[jj][r];
            s[jj][0] += hv * w.x; s[jj][1] += hv * w.y;
            s[jj][2] += hv * w.z; s[jj][3] += hv * w.w;
        }
    }
#pragma unroll
    for (int jj = 0; jj < 8; jj++) {
#pragma unroll
        for (int u = 0; u < 4; u++) {
            int k = k0 + u;
            int head = k >> 7, d = k & 127;
            int qi = (jg + jj) * 4 + head;
            float q = s[jj][u] * QSCALE;
            __half h = __float2half_rn(q);
            g_Qh[((size_t)b * QROWS + qi) * KD + d] = h;
            g_Ql[((size_t)b * QROWS + qi) * KD + d] =
                __float2half_rn(q - __half2float(h));
        }
    }
}

// ---------------- fused attention kernel (fp16 2-pass) ----------------------
#define OFF_QH   0          // 128 x 68 u32 = 34816
#define OFF_QL   34816
#define OFF_KH   69632      // 64 x 68 u32 = 17408
#define OFF_VH   87040      // 136 x 36 u32 = 19584  [v][n]
#define OFF_KSTA 106624     // f32[8192]  raw K chunk
#define OFF_VSTA 139392     // f32[8320]  raw V chunk
#define OFF_KEEP 172672     // f32[256]   keep for all 4 chunks
#define SM_TOTAL 173696
__global__ void __launch_bounds__(256) fused_attn_kernel(
    const float* __restrict__ Kg, const float* __restrict__ Vg,
    const void* __restrict__ mk) {
    extern __shared__ unsigned char smraw[];
    unsigned* Qh32 = (unsigned*)(smraw + OFF_QH);
    unsigned* Ql32 = (unsigned*)(smraw + OFF_QL);
    unsigned* Kh32 = (unsigned*)(smraw + OFF_KH);
    unsigned* Vh32 = (unsigned*)(smraw + OFF_VH);
    float* Ksta    = (float*)(smraw + OFF_KSTA);
    float* Vsta    = (float*)(smraw + OFF_VSTA);
    float* keepAll = (float*)(smraw + OFF_KEEP);

    int split = blockIdx.x, b = blockIdx.y;
    int tid = threadIdx.x;
    int w = tid >> 5, l = tid & 31, g = l >> 2, t = l & 3;
    int m0 = w * 16;
    int nblk = split * (NV / NSPLIT);

    int rowA = l & 15;
    int colA = (l >> 4) * 4;
    int rowB = (l & 7) + ((l >> 4) << 3);
    int colB = ((l >> 3) & 1) * 4;

    unsigned QhU = (unsigned)__cvta_generic_to_shared(Qh32);
    unsigned QlU = (unsigned)__cvta_generic_to_shared(Ql32);
    unsigned KhU = (unsigned)__cvta_generic_to_shared(Kh32);
    unsigned VhU = (unsigned)__cvta_generic_to_shared(Vh32);
    unsigned KstaU = (unsigned)__cvta_generic_to_shared(Ksta);
    unsigned VstaU = (unsigned)__cvta_generic_to_shared(Vsta);

    unsigned aH  = QhU + (((m0 + rowA) * 68) + colA) * 4;
    unsigned aL  = QlU + (((m0 + rowA) * 68) + colA) * 4;
    unsigned bKh = KhU + ((rowB * 68) + colB) * 4;
    unsigned bVh = VhU + ((rowB * 36) + colB) * 4;
    unsigned bV2h = VhU + (((128 + (l & 7)) * 36) + colB) * 4;

    // ---- prologue: cp.async Q + chunk0 K/V; keep computed inline ----
    {
        const char* srcH = (const char*)((const unsigned*)g_Qh + (size_t)b * (QROWS * KD / 2));
        const char* srcL = (const char*)((const unsigned*)g_Ql + (size_t)b * (QROWS * KD / 2));
#pragma unroll
        for (int i = 0; i < 8; i++) {
            int idx = tid + i * 256;
            int r = idx >> 4, c16 = idx & 15;
            unsigned dofs = (unsigned)(r * 272 + c16 * 16);
            cpa16(QhU + dofs, srcH + idx * 16);
            cpa16(QlU + dofs, srcL + idx * 16);
        }
        const char* ksrc = (const char*)(Kg + ((size_t)b * NV + nblk) * KD);
        const char* vsrc = (const char*)(Vg + ((size_t)b * NV + nblk) * VD);
#pragma unroll
        for (int i = 0; i < 8; i++) {
            int off = (tid + i * 256) * 16;
            cpa16(KstaU + off, ksrc + off);
        }
#pragma unroll
        for (int i = 0; i < 9; i++) {
            int idx = tid + i * 256;
            if (idx < 2080) cpa16(VstaU + idx * 16, vsrc + idx * 16);
        }
        asm volatile("cp.async.commit_group;" ::: "memory");

        int gi = b * NV + nblk + tid;
        bool masked;
        if (g_flags[0])      masked = ((const unsigned short*)mk)[gi] != 0;
        else if (g_flags[1]) masked = ((const float*)mk)[gi]          != 0.0f;
        else if (g_flags[2]) masked = ((const unsigned char*)mk)[gi]  != 0;
        else                 masked = ((const int*)mk)[gi]            != 0;
        keepAll[tid] = masked ? 0.0f : 1.0f;
    }
    // ones/zero rows of V buf (v = 130..135), written once. fp16 1.0 = 0x3C00
    for (int i = tid; i < 192; i += 256) {
        int v = 130 + (i >> 5), np = i & 31;
        Vh32[v * 36 + np] = (v == 130) ? 0x3C003C00u : 0u;
    }

    float accO[17][4];
#pragma unroll
    for (int i = 0; i < 17; i++) { accO[i][0] = accO[i][1] = accO[i][2] = accO[i][3] = 0.0f; }

    for (int c = 0; c < NCHUNKS; c++) {
        asm volatile("cp.async.wait_group 0;" ::: "memory");
        __syncthreads();

        // ---- K convert: f32 -> plain fp16 [n][d] stride 68 u32 ----
#pragma unroll
        for (int i = 0; i < 8; i++) {
            int idx = tid + i * 256;
            int n = idx >> 5;
            int d4 = (idx & 31) * 4;
            float4 v = *(const float4*)(Ksta + n * 128 + d4);
            int o = n * 68 + (d4 >> 1);
            Kh32[o]     = pack2H(v.x, v.y);
            Kh32[o + 1] = pack2H(v.z, v.w);
        }
        // ---- V convert: [n][v] f32 -> plain fp16 [v][n] stride 36 u32 ----
#pragma unroll
        for (int i = 0; i < 17; i++) {
            int p = tid + i * 256;
            if (p < 4160) {
                int np = p / 130;
                int v = p - np * 130;
                float x = Vsta[(2 * np) * 130 + v];
                float y = Vsta[(2 * np + 1) * 130 + v];
                Vh32[v * 36 + np] = pack2H(x, y);
            }
        }
        __syncthreads();

        // ---- prefetch next chunk (overlaps MMAs below) ----
        if (c < NCHUNKS - 1) {
            int n1 = nblk + (c + 1) * CHUNK;
            const char* ksrc = (const char*)(Kg + ((size_t)b * NV + n1) * KD);
            const char* vsrc = (const char*)(Vg + ((size_t)b * NV + n1) * VD);
#pragma unroll
            for (int i = 0; i < 8; i++) {
                int off = (tid + i * 256) * 16;
                cpa16(KstaU + off, ksrc + off);
            }
#pragma unroll
            for (int i = 0; i < 9; i++) {
                int idx = tid + i * 256;
                if (idx < 2080) cpa16(VstaU + idx * 16, vsrc + idx * 16);
            }
            asm volatile("cp.async.commit_group;" ::: "memory");
        }

        const float* keepc = keepAll + c * 64;

        // ---- QK: S = (Qh + Ql) K^T, 2-pass fp16, warp tile 16q x 64n ----
        float accS[8][4];
#pragma unroll
        for (int i = 0; i < 8; i++) { accS[i][0] = accS[i][1] = accS[i][2] = accS[i][3] = 0.0f; }

#pragma unroll
        for (int ks = 0; ks < 8; ks++) {
            unsigned ah0, ah1, ah2, ah3, al0, al1, al2, al3;
            LDSM_X4(ah0, ah1, ah2, ah3, aH + ks * 32);
            LDSM_X4(al0, al1, al2, al3, aL + ks * 32);
#pragma unroll
            for (int ntp = 0; ntp < 4; ntp++) {
                unsigned h0, h1, h2, h3;
                LDSM_X4(h0, h1, h2, h3, bKh + ntp * 4352 + ks * 32);
                MMA4(accS[2 * ntp], ah0, ah1, ah2, ah3, h0, h1);
                MMA4(accS[2 * ntp], al0, al1, al2, al3, h0, h1);
                MMA4(accS[2 * ntp + 1], ah0, ah1, ah2, ah3, h2, h3);
                MMA4(accS[2 * ntp + 1], al0, al1, al2, al3, h2, h3);
            }
        }

        // ---- epilogue: P = exp2(S - PBIAS)*keep, split to fp16 hi/lo ----
        unsigned phA[8], phB[8], plA[8], plB[8];
#pragma unroll
        for (int nt = 0; nt < 8; nt++) {
            int c0 = nt * 8 + 2 * t;
            float k0f = keepc[c0], k1f = keepc[c0 + 1];
            float p0 = exp2f(accS[nt][0] - PBIAS) * k0f;
            float p1 = exp2f(accS[nt][1] - PBIAS) * k1f;
            float p2 = exp2f(accS[nt][2] - PBIAS) * k0f;
            float p3 = exp2f(accS[nt][3] - PBIAS) * k1f;
            splitpackH(p0, p1, phA[nt], plA[nt]);
            splitpackH(p2, p3, phB[nt], plB[nt]);
        }

        // ---- PV: O += (Ph + Pl) @ [V|1]^T, 2-pass fp16 ----
#pragma unroll
        for (int ks = 0; ks < 4; ks++) {
            unsigned ah0 = phA[2 * ks], ah1 = phB[2 * ks];
            unsigned ah2 = phA[2 * ks + 1], ah3 = phB[2 * ks + 1];
            unsigned al0 = plA[2 * ks], al1 = plB[2 * ks];
            unsigned al2 = plA[2 * ks + 1], al3 = plB[2 * ks + 1];
#pragma unroll
            for (int vtp = 0; vtp < 8; vtp++) {
                unsigned h0, h1, h2, h3;
                LDSM_X4(h0, h1, h2, h3, bVh + vtp * 2304 + ks * 32);
                MMA4(accO[2 * vtp], ah0, ah1, ah2, ah3, h0, h1);
                MMA4(accO[2 * vtp], al0, al1, al2, al3, h0, h1);
                MMA4(accO[2 * vtp + 1], ah0, ah1, ah2, ah3, h2, h3);
                MMA4(accO[2 * vtp + 1], al0, al1, al2, al3, h2, h3);
            }
            { // tail tile v = 128..135 (includes ones column @130)
                unsigned h0, h1;
                LDSM_X2(h0, h1, bV2h + ks * 32);
                MMA4(accO[16], ah0, ah1, ah2, ah3, h0, h1);
                MMA4(accO[16], al0, al1, al2, al3, h0, h1);
            }
        }
    }

    // accumulate O tile directly into g_osum
    float* orow0 = g_osum + ((size_t)b * QROWS + m0 + g) * OST;
    float* orow1 = orow0 + 8 * OST;
#pragma unroll
    for (int vt = 0; vt < 17; vt++) {
        int v0 = vt * 8 + 2 * t;
        redadd(orow0 + v0,     accO[vt][0]);
        redadd(orow0 + v0 + 1, accO[vt][1]);
        redadd(orow1 + v0,     accO[vt][2]);
        redadd(orow1 + v0 + 1, accO[vt][3]);
    }
}

// ---------------- kernel C: per-batch-half normalize + MLP -----------------
__global__ void __launch_bounds__(256) mlp_kernel(
    const float* __restrict__ W3, const float* __restrict__ b3,
    const float* __restrict__ W4, const float* __restrict__ b4,
    const float* __restrict__ W5, const float* __restrict__ b5,
    float* __restrict__ out) {
    __shared__ float os2[64 * 136];    // 16 joints x 4 heads x 136
    __shared__ float rcp[64];
    __shared__ float h1[16 * 64];
    __shared__ float h2[16 * 32];
    int bid = blockIdx.x;            // b*2 + half
    int b = bid >> 1, half = bid & 1;
    int tid = threadIdx.x;
    size_t base4 = (((size_t)b * QROWS + half * 64) * OST) / 4;

    for (int i4 = tid; i4 < 2176; i4 += 256)
        *(float4*)&os2[i4 * 4] = ((const float4*)g_osum)[base4 + i4];
    __syncthreads();
    if (tid < 64) rcp[tid] = __frcp_rn(os2[tid * 136 + 130]);
    __syncthreads();
    for (int idx = tid; idx < 64 * 130; idx += 256) {
        int r = idx / 130, v = idx - r * 130;
        os2[r * 136 + v] *= rcp[r];
    }
    __syncthreads();

    // layer 1: [16 j][520] @ W3[520][64]
    {
        int o = tid & 63, jq4 = tid >> 6;
        float s0 = b3[o], s1 = s0, s2 = s0, s3 = s0;
        for (int h = 0; h < 4; h++) {
            const float* osr = os2 + (jq4 * 16 + h) * 136;
            const float* w3r = W3 + h * 130 * 64 + o;
            for (int v = 0; v < 130; v++) {
                float wv = w3r[v * 64];
                s0 += osr[v] * wv;
                s1 += osr[v + 544] * wv;
                s2 += osr[v + 1088] * wv;
                s3 += osr[v + 1632] * wv;
            }
        }
        int j0 = jq4 * 4;
        h1[(j0 + 0) * 64 + o] = fmaxf(s0, 0.0f);
        h1[(j0 + 1) * 64 + o] = fmaxf(s1, 0.0f);
        h1[(j0 + 2) * 64 + o] = fmaxf(s2, 0.0f);
        h1[(j0 + 3) * 64 + o] = fmaxf(s3, 0.0f);
    }
    __syncthreads();

#pragma unroll
    for (int rep = 0; rep < 2; rep++) {
        int it = tid + rep * 256;
        int j = it >> 5, o = it & 31;
        float s = b4[o];
#pragma unroll
        for (int r = 0; r < 64; r++) s += h1[j * 64 + r] * W4[r * 32 + o];
        h2[j * 32 + o] = fmaxf(s, 0.0f);
    }
    __syncthreads();

    int wid = tid >> 5, lane = tid & 31;
#pragma unroll
    for (int rep = 0; rep < 2; rep++) {
        int j = wid + rep * 8;
        float v = h2[j * 32 + lane] * W5[lane];
#pragma unroll
        for (int off = 16; off; off >>= 1) v += __shfl_down_sync(0xffffffffu, v, off);
        if (lane == 0) out[b * JJ + half * 16 + j] = v + b5[0];
    }
    // reset mask-dtype flags for next graph replay
    if (bid == 0 && tid < 3) g_flags[tid] = 0;
}

// ---------------- launch ----------------------------------------------------
extern "C" void kernel_launch(void* const* d_in, const int* in_sizes, int n_in,
                              void* d_out, int out_size) {
    const float* jq = (const float*)d_in[0];
    const float* Kg = (const float*)d_in[1];
    const float* Vg = (const float*)d_in[2];
    const void*  mk = d_in[3];
    const float* W1 = (const float*)d_in[4];
    const float* b1 = (const float*)d_in[5];
    const float* W2 = (const float*)d_in[6];
    const float* b2 = (const float*)d_in[7];
    const float* W3 = (const float*)d_in[8];
    const float* b3 = (const float*)d_in[9];
    const float* W4 = (const float*)d_in[10];
    const float* b4 = (const float*)d_in[11];
    const float* W5 = (const float*)d_in[12];
    const float* b5 = (const float*)d_in[13];
    float* out = (float*)d_out;

    classify_mask<<<64, 256>>>((const uint4*)mk);
    zero_osum<<<(BB * QROWS * OST / 4) / 256, 256>>>();
    encoder_kernel<<<BB * 4, 128>>>(jq, W1, b1, W2, b2);

    cudaFuncSetAttribute(fused_attn_kernel,
                         cudaFuncAttributeMaxDynamicSharedMemorySize, SM_TOTAL);
    dim3 g1(NSPLIT, BB);
    fused_attn_kernel<<<g1, 256, SM_TOTAL>>>(Kg, Vg, mk);

    mlp_kernel<<<BB * 2, 256>>>(W3, b3, W4, b4, W5, b5, out);
}

// round 17
// speedup vs baseline: 1.4391x; 1.1899x over previous
#include <cuda_runtime.h>
#include <cuda_bf16.h>
#include <cuda_fp16.h>
#include <math.h>

#define BB 64
#define JJ 32
#define NV 4096
#define QD 130
#define KD 128
#define VD 130
#define HH 4
#define QROWS 128              // J*H rows of q per batch
#define OST 136                // osum row stride (130 vals + denom @130 + pad)
#define NSPLIT 16              // n-splits (accumulated via red.global.add)
#define CHUNK 64
#define NCHUNKS ((NV / NSPLIT) / CHUNK)   // 4
// fold log2(e)/sqrt(128) into q so p = exp2f(score)
#define QSCALE (1.4426950408889634f / 11.313708498984761f)
#define PBIAS 3.0f             // p = exp2(S - PBIAS); cancels in normalization

// ---------------- device scratch (static: no runtime allocation) ----------
__device__ __half g_Q[BB * QROWS * KD];            // [b][q][d] fp16
__device__ float g_osum[(size_t)BB * QROWS * OST]; // accumulated O (4.25 MB)
__device__ int   g_flags[3];                       // mask-dtype evidence flags

// pack two floats -> fp16x2 u32 (x -> low half, y -> high half)
__device__ __forceinline__ unsigned pack2H(float x, float y) {
    unsigned r;
    asm("cvt.rn.f16x2.f32 %0, %1, %2;" : "=r"(r) : "f"(y), "f"(x));
    return r;
}

#define MMA4(C, A0, A1, A2, A3, B0, B1) \
    asm volatile("mma.sync.aligned.m16n8k16.row.col.f32.f16.f16.f32 " \
        "{%0,%1,%2,%3}, {%4,%5,%6,%7}, {%8,%9}, {%0,%1,%2,%3};" \
        : "+f"((C)[0]), "+f"((C)[1]), "+f"((C)[2]), "+f"((C)[3]) \
        : "r"(A0), "r"(A1), "r"(A2), "r"(A3), "r"(B0), "r"(B1))

#define LDSM_X4(R0, R1, R2, R3, ADDR) \
    asm volatile("ldmatrix.sync.aligned.m8n8.x4.shared.b16 {%0,%1,%2,%3}, [%4];" \
        : "=r"(R0), "=r"(R1), "=r"(R2), "=r"(R3) : "r"(ADDR))

#define LDSM_X2(R0, R1, ADDR) \
    asm volatile("ldmatrix.sync.aligned.m8n8.x2.shared.b16 {%0,%1}, [%2];" \
        : "=r"(R0), "=r"(R1) : "r"(ADDR))

__device__ __forceinline__ void cpa16(unsigned dst, const void* src) {
    asm volatile("cp.async.cg.shared.global [%0], [%1], 16;" :: "r"(dst), "l"(src));
}

__device__ __forceinline__ void redadd(float* p, float v) {
    asm volatile("red.global.add.f32 [%0], %1;" :: "l"(p), "f"(v) : "memory");
}

// ---------------- mask dtype detection (deterministic, data-driven) -------
__global__ void classify_mask(const uint4* __restrict__ m) {
    int gid = blockIdx.x * 256 + threadIdx.x;   // 0..16383
    uint4 v = m[gid];
    unsigned wrd[4] = {v.x, v.y, v.z, v.w};
    bool l0 = false, l1 = false, l2 = false;
#pragma unroll
    for (int wI = 0; wI < 4; wI++) {
        unsigned x = wrd[wI];
        unsigned b0 = x & 0xFF, b1 = (x >> 8) & 0xFF, b2 = (x >> 16) & 0xFF, b3 = x >> 24;
        if (b1 == 0x3F) l0 = true;
        if (b0 == 0x3F || b1 == 0x3F || b2 == 0x3F || b3 == 0x3F) l1 = true;
        if (b1 | b2 | b3) l2 = true;
    }
    unsigned m0 = __ballot_sync(0xFFFFFFFFu, l0);
    unsigned m1 = __ballot_sync(0xFFFFFFFFu, l1);
    unsigned m2 = __ballot_sync(0xFFFFFFFFu, l2);
    if ((threadIdx.x & 31) == 0) {
        if (m0) atomicOr(&g_flags[0], 1);
        if (m1) atomicOr(&g_flags[1], 1);
        if (m2) atomicOr(&g_flags[2], 1);
    }
}

// zero the O accumulator (must precede fused_attn each replay)
__global__ void __launch_bounds__(256) zero_osum() {
    size_t i4 = (size_t)blockIdx.x * 256 + threadIdx.x;
    ((float4*)g_osum)[i4] = make_float4(0.f, 0.f, 0.f, 0.f);
}

// ---------------- kernel A: q encoder MLP, 8 joints per block --------------
__global__ void __launch_bounds__(128) encoder_kernel(
    const float* __restrict__ jq,
    const float* __restrict__ W1, const float* __restrict__ b1,
    const float* __restrict__ W2, const float* __restrict__ b2) {
    __shared__ float xs[8][132];
    __shared__ float hs[8][68];
    int bid = blockIdx.x;            // b*4 + jg
    int b = bid >> 2, jg = (bid & 3) * 8;
    int tid = threadIdx.x;

    for (int idx = tid; idx < 8 * QD; idx += 128) {
        int jj = idx / QD, d = idx - jj * QD;
        xs[jj][d] = jq[((size_t)(b * JJ + jg + jj)) * QD + d];
    }
    __syncthreads();
    {
        int o = tid & 63, jb = tid >> 6;
        float s0 = b1[o], s1 = s0, s2 = s0, s3 = s0;
        for (int r = 0; r < QD; r++) {
            float wv = W1[r * 64 + o];
            s0 += xs[jb][r] * wv;
            s1 += xs[jb + 2][r] * wv;
            s2 += xs[jb + 4][r] * wv;
            s3 += xs[jb + 6][r] * wv;
        }
        hs[jb][o]     = fmaxf(s0, 0.0f);
        hs[jb + 2][o] = fmaxf(s1, 0.0f);
        hs[jb + 4][o] = fmaxf(s2, 0.0f);
        hs[jb + 6][o] = fmaxf(s3, 0.0f);
    }
    __syncthreads();
    int k0 = tid * 4;
    float s[8][4];
    float bb0 = b2[k0], bb1 = b2[k0 + 1], bb2 = b2[k0 + 2], bb3 = b2[k0 + 3];
#pragma unroll
    for (int jj = 0; jj < 8; jj++) {
        s[jj][0] = bb0; s[jj][1] = bb1; s[jj][2] = bb2; s[jj][3] = bb3;
    }
    for (int r = 0; r < 64; r++) {
        float4 w = *(const float4*)(W2 + r * 512 + k0);
#pragma unroll
        for (int jj = 0; jj < 8; jj++) {
            float hv = hs[jj][r];
            s[jj][0] += hv * w.x; s[jj][1] += hv * w.y;
            s[jj][2] += hv * w.z; s[jj][3] += hv * w.w;
        }
    }
#pragma unroll
    for (int jj = 0; jj < 8; jj++) {
#pragma unroll
        for (int u = 0; u < 4; u++) {
            int k = k0 + u;
            int head = k >> 7, d = k & 127;
            int qi = (jg + jj) * 4 + head;
            g_Q[((size_t)b * QROWS + qi) * KD + d] = __float2half_rn(s[jj][u] * QSCALE);
        }
    }
}

// ---------------- fused attention kernel (plain fp16, single pass) ---------
#define OFF_Q    0          // 128 x 68 u32 = 34816
#define OFF_KH   34816      // 64 x 68 u32 = 17408
#define OFF_VH   52224      // 136 x 36 u32 = 19584  [v][n]
#define OFF_KSTA 71808      // f32[8192]  raw K chunk (32768)
#define OFF_VSTA 104576     // f32[8320]  raw V chunk (33280)
#define OFF_KEEP 137856     // f32[256]   keep for all 4 chunks
#define SM_TOTAL 138880
__global__ void __launch_bounds__(256) fused_attn_kernel(
    const float* __restrict__ Kg, const float* __restrict__ Vg,
    const void* __restrict__ mk) {
    extern __shared__ unsigned char smraw[];
    unsigned* Q32  = (unsigned*)(smraw + OFF_Q);
    unsigned* Kh32 = (unsigned*)(smraw + OFF_KH);
    unsigned* Vh32 = (unsigned*)(smraw + OFF_VH);
    float* Ksta    = (float*)(smraw + OFF_KSTA);
    float* Vsta    = (float*)(smraw + OFF_VSTA);
    float* keepAll = (float*)(smraw + OFF_KEEP);

    int split = blockIdx.x, b = blockIdx.y;
    int tid = threadIdx.x;
    int w = tid >> 5, l = tid & 31, g = l >> 2, t = l & 3;
    int m0 = w * 16;
    int nblk = split * (NV / NSPLIT);

    int rowA = l & 15;
    int colA = (l >> 4) * 4;
    int rowB = (l & 7) + ((l >> 4) << 3);
    int colB = ((l >> 3) & 1) * 4;

    unsigned QU  = (unsigned)__cvta_generic_to_shared(Q32);
    unsigned KhU = (unsigned)__cvta_generic_to_shared(Kh32);
    unsigned VhU = (unsigned)__cvta_generic_to_shared(Vh32);
    unsigned KstaU = (unsigned)__cvta_generic_to_shared(Ksta);
    unsigned VstaU = (unsigned)__cvta_generic_to_shared(Vsta);

    unsigned aH  = QU + (((m0 + rowA) * 68) + colA) * 4;
    unsigned bKh = KhU + ((rowB * 68) + colB) * 4;
    unsigned bVh = VhU + ((rowB * 36) + colB) * 4;
    unsigned bV2h = VhU + (((128 + (l & 7)) * 36) + colB) * 4;

    // ---- prologue: cp.async Q + chunk0 K/V; keep computed inline ----
    {
        const char* srcQ = (const char*)((const unsigned*)g_Q + (size_t)b * (QROWS * KD / 2));
#pragma unroll
        for (int i = 0; i < 8; i++) {
            int idx = tid + i * 256;
            int r = idx >> 4, c16 = idx & 15;
            unsigned dofs = (unsigned)(r * 272 + c16 * 16);
            cpa16(QU + dofs, srcQ + idx * 16);
        }
        const char* ksrc = (const char*)(Kg + ((size_t)b * NV + nblk) * KD);
        const char* vsrc = (const char*)(Vg + ((size_t)b * NV + nblk) * VD);
#pragma unroll
        for (int i = 0; i < 8; i++) {
            int off = (tid + i * 256) * 16;
            cpa16(KstaU + off, ksrc + off);
        }
#pragma unroll
        for (int i = 0; i < 9; i++) {
            int idx = tid + i * 256;
            if (idx < 2080) cpa16(VstaU + idx * 16, vsrc + idx * 16);
        }
        asm volatile("cp.async.commit_group;" ::: "memory");

        int gi = b * NV + nblk + tid;
        bool masked;
        if (g_flags[0])      masked = ((const unsigned short*)mk)[gi] != 0;
        else if (g_flags[1]) masked = ((const float*)mk)[gi]          != 0.0f;
        else if (g_flags[2]) masked = ((const unsigned char*)mk)[gi]  != 0;
        else                 masked = ((const int*)mk)[gi]            != 0;
        keepAll[tid] = masked ? 0.0f : 1.0f;
    }
    // ones/zero rows of V buf (v = 130..135), written once. fp16 1.0 = 0x3C00
    for (int i = tid; i < 192; i += 256) {
        int v = 130 + (i >> 5), np = i & 31;
        Vh32[v * 36 + np] = (v == 130) ? 0x3C003C00u : 0u;
    }

    float accO[17][4];
#pragma unroll
    for (int i = 0; i < 17; i++) { accO[i][0] = accO[i][1] = accO[i][2] = accO[i][3] = 0.0f; }

    for (int c = 0; c < NCHUNKS; c++) {
        asm volatile("cp.async.wait_group 0;" ::: "memory");
        __syncthreads();

        // ---- K convert: f32 -> plain fp16 [n][d] stride 68 u32 ----
#pragma unroll
        for (int i = 0; i < 8; i++) {
            int idx = tid + i * 256;
            int n = idx >> 5;
            int d4 = (idx & 31) * 4;
            float4 v = *(const float4*)(Ksta + n * 128 + d4);
            int o = n * 68 + (d4 >> 1);
            Kh32[o]     = pack2H(v.x, v.y);
            Kh32[o + 1] = pack2H(v.z, v.w);
        }
        // ---- V convert: [n][v] f32 -> plain fp16 [v][n] stride 36 u32 ----
#pragma unroll
        for (int i = 0; i < 17; i++) {
            int p = tid + i * 256;
            if (p < 4160) {
                int np = p / 130;
                int v = p - np * 130;
                float x = Vsta[(2 * np) * 130 + v];
                float y = Vsta[(2 * np + 1) * 130 + v];
                Vh32[v * 36 + np] = pack2H(x, y);
            }
        }
        __syncthreads();

        // ---- prefetch next chunk (overlaps MMAs below) ----
        if (c < NCHUNKS - 1) {
            int n1 = nblk + (c + 1) * CHUNK;
            const char* ksrc = (const char*)(Kg + ((size_t)b * NV + n1) * KD);
            const char* vsrc = (const char*)(Vg + ((size_t)b * NV + n1) * VD);
#pragma unroll
            for (int i = 0; i < 8; i++) {
                int off = (tid + i * 256) * 16;
                cpa16(KstaU + off, ksrc + off);
            }
#pragma unroll
            for (int i = 0; i < 9; i++) {
                int idx = tid + i * 256;
                if (idx < 2080) cpa16(VstaU + idx * 16, vsrc + idx * 16);
            }
            asm volatile("cp.async.commit_group;" ::: "memory");
        }

        const float* keepc = keepAll + c * 64;

        // ---- QK: S = Q K^T, plain fp16, warp tile 16q x 64n ----
        float accS[8][4];
#pragma unroll
        for (int i = 0; i < 8; i++) { accS[i][0] = accS[i][1] = accS[i][2] = accS[i][3] = 0.0f; }

#pragma unroll
        for (int ks = 0; ks < 8; ks++) {
            unsigned ah0, ah1, ah2, ah3;
            LDSM_X4(ah0, ah1, ah2, ah3, aH + ks * 32);
#pragma unroll
            for (int ntp = 0; ntp < 4; ntp++) {
                unsigned h0, h1, h2, h3;
                LDSM_X4(h0, h1, h2, h3, bKh + ntp * 4352 + ks * 32);
                MMA4(accS[2 * ntp], ah0, ah1, ah2, ah3, h0, h1);
                MMA4(accS[2 * ntp + 1], ah0, ah1, ah2, ah3, h2, h3);
            }
        }

        // ---- epilogue: P = exp2(S - PBIAS)*keep -> fp16 fragments ----
        unsigned phA[8], phB[8];
#pragma unroll
        for (int nt = 0; nt < 8; nt++) {
            int c0 = nt * 8 + 2 * t;
            float k0f = keepc[c0], k1f = keepc[c0 + 1];
            float p0 = exp2f(accS[nt][0] - PBIAS) * k0f;
            float p1 = exp2f(accS[nt][1] - PBIAS) * k1f;
            float p2 = exp2f(accS[nt][2] - PBIAS) * k0f;
            float p3 = exp2f(accS[nt][3] - PBIAS) * k1f;
            phA[nt] = pack2H(p0, p1);
            phB[nt] = pack2H(p2, p3);
        }

        // ---- PV: O += P @ [V|1]^T, plain fp16 ----
#pragma unroll
        for (int ks = 0; ks < 4; ks++) {
            unsigned ah0 = phA[2 * ks], ah1 = phB[2 * ks];
            unsigned ah2 = phA[2 * ks + 1], ah3 = phB[2 * ks + 1];
#pragma unroll
            for (int vtp = 0; vtp < 8; vtp++) {
                unsigned h0, h1, h2, h3;
                LDSM_X4(h0, h1, h2, h3, bVh + vtp * 2304 + ks * 32);
                MMA4(accO[2 * vtp], ah0, ah1, ah2, ah3, h0, h1);
                MMA4(accO[2 * vtp + 1], ah0, ah1, ah2, ah3, h2, h3);
            }
            { // tail tile v = 128..135 (includes ones column @130)
                unsigned h0, h1;
                LDSM_X2(h0, h1, bV2h + ks * 32);
                MMA4(accO[16], ah0, ah1, ah2, ah3, h0, h1);
            }
        }
    }

    // accumulate O tile directly into g_osum
    float* orow0 = g_osum + ((size_t)b * QROWS + m0 + g) * OST;
    float* orow1 = orow0 + 8 * OST;
#pragma unroll
    for (int vt = 0; vt < 17; vt++) {
        int v0 = vt * 8 + 2 * t;
        redadd(orow0 + v0,     accO[vt][0]);
        redadd(orow0 + v0 + 1, accO[vt][1]);
        redadd(orow1 + v0,     accO[vt][2]);
        redadd(orow1 + v0 + 1, accO[vt][3]);
    }
}

// ---------------- kernel C: per-batch-half normalize + MLP -----------------
__global__ void __launch_bounds__(256) mlp_kernel(
    const float* __restrict__ W3, const float* __restrict__ b3,
    const float* __restrict__ W4, const float* __restrict__ b4,
    const float* __restrict__ W5, const float* __restrict__ b5,
    float* __restrict__ out) {
    __shared__ float os2[64 * 136];    // 16 joints x 4 heads x 136
    __shared__ float rcp[64];
    __shared__ float h1[16 * 64];
    __shared__ float h2[16 * 32];
    int bid = blockIdx.x;            // b*2 + half
    int b = bid >> 1, half = bid & 1;
    int tid = threadIdx.x;
    size_t base4 = (((size_t)b * QROWS + half * 64) * OST) / 4;

    for (int i4 = tid; i4 < 2176; i4 += 256)
        *(float4*)&os2[i4 * 4] = ((const float4*)g_osum)[base4 + i4];
    __syncthreads();
    if (tid < 64) rcp[tid] = __frcp_rn(os2[tid * 136 + 130]);
    __syncthreads();
    for (int idx = tid; idx < 64 * 130; idx += 256) {
        int r = idx / 130, v = idx - r * 130;
        os2[r * 136 + v] *= rcp[r];
    }
    __syncthreads();

    // layer 1: [16 j][520] @ W3[520][64]
    {
        int o = tid & 63, jq4 = tid >> 6;
        float s0 = b3[o], s1 = s0, s2 = s0, s3 = s0;
        for (int h = 0; h < 4; h++) {
            const float* osr = os2 + (jq4 * 16 + h) * 136;
            const float* w3r = W3 + h * 130 * 64 + o;
            for (int v = 0; v < 130; v++) {
                float wv = w3r[v * 64];
                s0 += osr[v] * wv;
                s1 += osr[v + 544] * wv;
                s2 += osr[v + 1088] * wv;
                s3 += osr[v + 1632] * wv;
            }
        }
        int j0 = jq4 * 4;
        h1[(j0 + 0) * 64 + o] = fmaxf(s0, 0.0f);
        h1[(j0 + 1) * 64 + o] = fmaxf(s1, 0.0f);
        h1[(j0 + 2) * 64 + o] = fmaxf(s2, 0.0f);
        h1[(j0 + 3) * 64 + o] = fmaxf(s3, 0.0f);
    }
    __syncthreads();

#pragma unroll
    for (int rep = 0; rep < 2; rep++) {
        int it = tid + rep * 256;
        int j = it >> 5, o = it & 31;
        float s = b4[o];
#pragma unroll
        for (int r = 0; r < 64; r++) s += h1[j * 64 + r] * W4[r * 32 + o];
        h2[j * 32 + o] = fmaxf(s, 0.0f);
    }
    __syncthreads();

    int wid = tid >> 5, lane = tid & 31;
#pragma unroll
    for (int rep = 0; rep < 2; rep++) {
        int j = wid + rep * 8;
        float v = h2[j * 32 + lane] * W5[lane];
#pragma unroll
        for (int off = 16; off; off >>= 1) v += __shfl_down_sync(0xffffffffu, v, off);
        if (lane == 0) out[b * JJ + half * 16 + j] = v + b5[0];
    }
    // reset mask-dtype flags for next graph replay
    if (bid == 0 && tid < 3) g_flags[tid] = 0;
}

// ---------------- launch ----------------------------------------------------
extern "C" void kernel_launch(void* const* d_in, const int* in_sizes, int n_in,
                              void* d_out, int out_size) {
    const float* jq = (const float*)d_in[0];
    const float* Kg = (const float*)d_in[1];
    const float* Vg = (const float*)d_in[2];
    const void*  mk = d_in[3];
    const float* W1 = (const float*)d_in[4];
    const float* b1 = (const float*)d_in[5];
    const float* W2 = (const float*)d_in[6];
    const float* b2 = (const float*)d_in[7];
    const float* W3 = (const float*)d_in[8];
    const float* b3 = (const float*)d_in[9];
    const float* W4 = (const float*)d_in[10];
    const float* b4 = (const float*)d_in[11];
    const float* W5 = (const float*)d_in[12];
    const float* b5 = (const float*)d_in[13];
    float* out = (float*)d_out;

    classify_mask<<<64, 256>>>((const uint4*)mk);
    zero_osum<<<(BB * QROWS * OST / 4) / 256, 256>>>();
    encoder_kernel<<<BB * 4, 128>>>(jq, W1, b1, W2, b2);

    cudaFuncSetAttribute(fused_attn_kernel,
                         cudaFuncAttributeMaxDynamicSharedMemorySize, SM_TOTAL);
    dim3 g1(NSPLIT, BB);
    fused_attn_kernel<<<g1, 256, SM_TOTAL>>>(Kg, Vg, mk);

    mlp_kernel<<<BB * 2, 256>>>(W3, b3, W4, b4, W5, b5, out);
}